// round 5
// baseline (speedup 1.0000x reference)
#include <cuda_runtime.h>

// Half-lattice hop operator, 6 threads/site x 2 rows/thread:
//   out = DIAG*psi - 0.5 * sum_mu ( K_fwd[mu] @ psi(fwd nbr) + K_bwd[mu] @ psi(bwd nbr) )
// T=Z=Y=16, X/2=8, D=12 complex. mu<3: periodic roll; mu=3: parity-gated X hop.

#define DD 12
#define NV (16*16*16*8)          // 32768 sites
#define DIAGC 4.5f
#define KSTRIDE4 (NV*DD*DD/4)    // float4 per (mu) slab

__global__ __launch_bounds__(192, 3)
void hop_kernel(const float* __restrict__ psr, const float* __restrict__ psi_,
                const float* __restrict__ Kfr, const float* __restrict__ Kfi,
                const float* __restrict__ Kbr, const float* __restrict__ Kbi,
                float* __restrict__ out)
{
    const int i  = threadIdx.x;           // 0..5 -> rows 2i, 2i+1
    const int ty = threadIdx.y;           // 0..31 site within block
    const int site = blockIdx.x * 32 + ty;

    // site bits: x [0:3), y [3:7), z [7:11), t [11:15)
    const int x = site & 7;
    const int y = (site >> 3) & 15;
    const int z = (site >> 7) & 15;
    const int t = (site >> 11) & 15;
    const int r = (t + z + y) & 1;

    // neighbor float4-offsets into psi arrays (site*12 floats = site*3 float4)
    const unsigned nn[8] = {
        ((site & ~(15<<11)) | (((t+1)&15)<<11)) * 3u,   // T fwd
        ((site & ~(15<<11)) | (((t+15)&15)<<11)) * 3u,  // T bwd
        ((site & ~(15<<7))  | (((z+1)&15)<<7)) * 3u,    // Z fwd
        ((site & ~(15<<7))  | (((z+15)&15)<<7)) * 3u,   // Z bwd
        ((site & ~(15<<3))  | (((y+1)&15)<<3)) * 3u,    // Y fwd
        ((site & ~(15<<3))  | (((y+15)&15)<<3)) * 3u,   // Y bwd
        (unsigned)(r ? ((site & ~7) | ((x+1)&7)) : site) * 3u,   // X fwd iff r==1
        (unsigned)(r ? site : ((site & ~7) | ((x+7)&7))) * 3u    // X bwd iff r==0
    };

    // this thread's 2-row K chunk: float4 offset site*36 + i*6 (rows 2i,2i+1 = 6 quads)
    const unsigned kb = (unsigned)site * 36u + (unsigned)i * 6u;
    const float4* pr4 = reinterpret_cast<const float4*>(psr);
    const float4* pi4 = reinterpret_cast<const float4*>(psi_);

    // accumulators: row A (2i) and row B (2i+1), each split in two chains
    float hrA0=0.f, hrA1=0.f, hiA0=0.f, hiA1=0.f;
    float hrB0=0.f, hrB1=0.f, hiB0=0.f, hiB1=0.f;

#pragma unroll
    for (int s = 0; s < 8; ++s) {
        const int mu = s >> 1;
        const float4* gr = reinterpret_cast<const float4*>((s & 1) ? Kbr : Kfr)
                           + mu * KSTRIDE4 + kb;
        const float4* gi = reinterpret_cast<const float4*>((s & 1) ? Kbi : Kfi)
                           + mu * KSTRIDE4 + kb;
        float4 kA[3], kB[3], lA[3], lB[3], vr[3], vi[3];
#pragma unroll
        for (int c = 0; c < 3; ++c) {
            kA[c] = __ldg(gr + c);       // row 2i   re
            kB[c] = __ldg(gr + 3 + c);   // row 2i+1 re
            lA[c] = __ldg(gi + c);       // row 2i   im
            lB[c] = __ldg(gi + 3 + c);   // row 2i+1 im
            vr[c] = __ldg(pr4 + nn[s] + c);
            vi[c] = __ldg(pi4 + nn[s] + c);
        }
#pragma unroll
        for (int c = 0; c < 3; ++c) {
            const float4 vrv = vr[c], viv = vi[c];
            // row A
            hrA0 = fmaf(kA[c].x, vrv.x, hrA0); hrA0 = fmaf(-lA[c].x, viv.x, hrA0);
            hiA0 = fmaf(kA[c].x, viv.x, hiA0); hiA0 = fmaf( lA[c].x, vrv.x, hiA0);
            hrA1 = fmaf(kA[c].y, vrv.y, hrA1); hrA1 = fmaf(-lA[c].y, viv.y, hrA1);
            hiA1 = fmaf(kA[c].y, viv.y, hiA1); hiA1 = fmaf( lA[c].y, vrv.y, hiA1);
            hrA0 = fmaf(kA[c].z, vrv.z, hrA0); hrA0 = fmaf(-lA[c].z, viv.z, hrA0);
            hiA0 = fmaf(kA[c].z, viv.z, hiA0); hiA0 = fmaf( lA[c].z, vrv.z, hiA0);
            hrA1 = fmaf(kA[c].w, vrv.w, hrA1); hrA1 = fmaf(-lA[c].w, viv.w, hrA1);
            hiA1 = fmaf(kA[c].w, viv.w, hiA1); hiA1 = fmaf( lA[c].w, vrv.w, hiA1);
            // row B
            hrB0 = fmaf(kB[c].x, vrv.x, hrB0); hrB0 = fmaf(-lB[c].x, viv.x, hrB0);
            hiB0 = fmaf(kB[c].x, viv.x, hiB0); hiB0 = fmaf( lB[c].x, vrv.x, hiB0);
            hrB1 = fmaf(kB[c].y, vrv.y, hrB1); hrB1 = fmaf(-lB[c].y, viv.y, hrB1);
            hiB1 = fmaf(kB[c].y, viv.y, hiB1); hiB1 = fmaf( lB[c].y, vrv.y, hiB1);
            hrB0 = fmaf(kB[c].z, vrv.z, hrB0); hrB0 = fmaf(-lB[c].z, viv.z, hrB0);
            hiB0 = fmaf(kB[c].z, viv.z, hiB0); hiB0 = fmaf( lB[c].z, vrv.z, hiB0);
            hrB1 = fmaf(kB[c].w, vrv.w, hrB1); hrB1 = fmaf(-lB[c].w, viv.w, hrB1);
            hiB1 = fmaf(kB[c].w, viv.w, hiB1); hiB1 = fmaf( lB[c].w, vrv.w, hiB1);
        }
    }

    const unsigned so = (unsigned)site * DD + (unsigned)(2 * i);
    const float2 pre = *reinterpret_cast<const float2*>(psr + so);
    const float2 pim = *reinterpret_cast<const float2*>(psi_ + so);
    float2 orv, oiv;
    orv.x = DIAGC * pre.x - 0.5f * (hrA0 + hrA1);
    orv.y = DIAGC * pre.y - 0.5f * (hrB0 + hrB1);
    oiv.x = DIAGC * pim.x - 0.5f * (hiA0 + hiA1);
    oiv.y = DIAGC * pim.y - 0.5f * (hiB0 + hiB1);
    *reinterpret_cast<float2*>(out + so)           = orv;
    *reinterpret_cast<float2*>(out + NV * DD + so) = oiv;
}

extern "C" void kernel_launch(void* const* d_in, const int* in_sizes, int n_in,
                              void* d_out, int out_size)
{
    const float* psr = (const float*)d_in[0];
    const float* psi = (const float*)d_in[1];
    const float* Kfr = (const float*)d_in[2];
    const float* Kfi = (const float*)d_in[3];
    const float* Kbr = (const float*)d_in[4];
    const float* Kbi = (const float*)d_in[5];
    float* out = (float*)d_out;

    dim3 block(6, 32);       // 6 row-pairs x 32 sites = 192 threads
    dim3 grid(NV / 32);      // 1024 blocks
    hop_kernel<<<grid, block>>>(psr, psi, Kfr, Kfi, Kbr, Kbi, out);
}

// round 6
// speedup vs baseline: 1.1140x; 1.1140x over previous
#include <cuda_runtime.h>

// Half-lattice hop operator:
//   out = DIAG*psi - 0.5 * sum_mu ( K_fwd[mu] @ psi(fwd nbr) + K_bwd[mu] @ psi(bwd nbr) )
// T=Z=Y=16, X/2=8, D=12 complex. mu<3: periodic roll on t/z/y; mu=3: parity-gated X hop.

#define DD 12
#define NV (16*16*16*8)   // 32768 sites
#define DIAGC 4.5f
#define KSTRIDE (NV * DD * DD)   // 4718592 floats, fits u32

__device__ __forceinline__ void cmatvec_row(
    const float* __restrict__ Krb, const float* __restrict__ Kib, unsigned ko,
    const float* __restrict__ prb, const float* __restrict__ pib, unsigned po,
    float& hr0, float& hi0, float& hr1, float& hi1)
{
    const float4* kr4 = reinterpret_cast<const float4*>(Krb + ko);
    const float4* ki4 = reinterpret_cast<const float4*>(Kib + ko);
    const float4* pr4 = reinterpret_cast<const float4*>(prb + po);
    const float4* pi4 = reinterpret_cast<const float4*>(pib + po);
#pragma unroll
    for (int c = 0; c < 3; ++c) {
        float4 kr = __ldcs(kr4 + c);   // K: streamed once, evict-first
        float4 ki = __ldcs(ki4 + c);
        float4 vr = __ldg(pr4 + c);    // psi: L2-resident, reused 13x
        float4 vi = __ldg(pi4 + c);
        hr0 = fmaf(kr.x, vr.x, hr0); hr0 = fmaf(-ki.x, vi.x, hr0);
        hi0 = fmaf(kr.x, vi.x, hi0); hi0 = fmaf( ki.x, vr.x, hi0);
        hr1 = fmaf(kr.y, vr.y, hr1); hr1 = fmaf(-ki.y, vi.y, hr1);
        hi1 = fmaf(kr.y, vi.y, hi1); hi1 = fmaf( ki.y, vr.y, hi1);
        hr0 = fmaf(kr.z, vr.z, hr0); hr0 = fmaf(-ki.z, vi.z, hr0);
        hi0 = fmaf(kr.z, vi.z, hi0); hi0 = fmaf( ki.z, vr.z, hi0);
        hr1 = fmaf(kr.w, vr.w, hr1); hr1 = fmaf(-ki.w, vi.w, hr1);
        hi1 = fmaf(kr.w, vi.w, hi1); hi1 = fmaf( ki.w, vr.w, hi1);
    }
}

__global__ __launch_bounds__(192, 6)
void hop_kernel(const float* __restrict__ psr, const float* __restrict__ psi,
                const float* __restrict__ Kfr, const float* __restrict__ Kfi,
                const float* __restrict__ Kbr, const float* __restrict__ Kbi,
                float* __restrict__ out)
{
    const int site = blockIdx.x * 16 + threadIdx.y;
    const int i = threadIdx.x;   // 0..11, output row

    // site bits: x [0:3), y [3:7), z [7:11), t [11:15)
    const int x = site & 7;
    const int y = (site >> 3) & 15;
    const int z = (site >> 7) & 15;
    const int t = (site >> 11) & 15;

    const int nTf = (site & ~(15 << 11)) | (((t + 1) & 15) << 11);
    const int nTb = (site & ~(15 << 11)) | (((t + 15) & 15) << 11);
    const int nZf = (site & ~(15 << 7))  | (((z + 1) & 15) << 7);
    const int nZb = (site & ~(15 << 7))  | (((z + 15) & 15) << 7);
    const int nYf = (site & ~(15 << 3))  | (((y + 1) & 15) << 3);
    const int nYb = (site & ~(15 << 3))  | (((y + 15) & 15) << 3);
    const int r = (t + z + y) & 1;
    const int nXf = r ? ((site & ~7) | ((x + 1) & 7)) : site;    // fwd hop iff r==1
    const int nXb = r ? site : ((site & ~7) | ((x + 7) & 7));    // bwd hop iff r==0

    const unsigned nf[4] = {(unsigned)nTf * DD, (unsigned)nZf * DD,
                            (unsigned)nYf * DD, (unsigned)nXf * DD};
    const unsigned nb[4] = {(unsigned)nTb * DD, (unsigned)nZb * DD,
                            (unsigned)nYb * DD, (unsigned)nXb * DD};

    float hr0 = 0.f, hi0 = 0.f, hr1 = 0.f, hi1 = 0.f;
    const unsigned rowoff = (unsigned)site * (DD * DD) + (unsigned)i * DD;

#pragma unroll
    for (int mu = 0; mu < 4; ++mu) {
        const unsigned ko = (unsigned)mu * KSTRIDE + rowoff;
        cmatvec_row(Kfr, Kfi, ko, psr, psi, nf[mu], hr0, hi0, hr1, hi1);
        cmatvec_row(Kbr, Kbi, ko, psr, psi, nb[mu], hr0, hi0, hr1, hi1);
    }

    const unsigned so = (unsigned)site * DD + (unsigned)i;
    const float pre = __ldg(psr + so);
    const float pim = __ldg(psi + so);
    __stcs(out + so,           DIAGC * pre - 0.5f * (hr0 + hr1));
    __stcs(out + NV * DD + so, DIAGC * pim - 0.5f * (hi0 + hi1));
}

extern "C" void kernel_launch(void* const* d_in, const int* in_sizes, int n_in,
                              void* d_out, int out_size)
{
    const float* psr = (const float*)d_in[0];
    const float* psi = (const float*)d_in[1];
    const float* Kfr = (const float*)d_in[2];
    const float* Kfi = (const float*)d_in[3];
    const float* Kbr = (const float*)d_in[4];
    const float* Kbi = (const float*)d_in[5];
    float* out = (float*)d_out;

    dim3 block(12, 16);      // 12 rows x 16 sites = 192 threads
    dim3 grid(NV / 16);      // 2048 blocks
    hop_kernel<<<grid, block>>>(psr, psi, Kfr, Kfi, Kbr, Kbi, out);
}